// round 1
// baseline (speedup 1.0000x reference)
#include <cuda_runtime.h>

#define BATCH   65536
#define DOF     7
#define NBASIS  5
#define KDIM    256
#define OUTC    42
#define STEPS   100   // TIME_STEPS - 1

// Scratch (no allocations allowed): GEMM output [B, 42] and RBF table.
__device__ float g_out42[(size_t)BATCH * OUTC];
__device__ float g_P[STEPS * 12];   // per step: (P0,P0,P1,P1,...,P4,P4,pad,pad)

typedef unsigned long long u64;

__device__ __forceinline__ u64 pack2(float a, float b) {
    u64 r; asm("mov.b64 %0,{%1,%2};" : "=l"(r) : "f"(a), "f"(b)); return r;
}
__device__ __forceinline__ u64 pack1(float a) { return pack2(a, a); }
__device__ __forceinline__ void unpack2(u64 v, float& a, float& b) {
    asm("mov.b64 {%0,%1},%2;" : "=f"(a), "=f"(b) : "l"(v));
}
__device__ __forceinline__ u64 fma2(u64 a, u64 b, u64 c) {
    u64 d; asm("fma.rn.f32x2 %0,%1,%2,%3;" : "=l"(d) : "l"(a), "l"(b), "l"(c)); return d;
}
__device__ __forceinline__ u64 mul2(u64 a, u64 b) {
    u64 d; asm("mul.rn.f32x2 %0,%1,%2;" : "=l"(d) : "l"(a), "l"(b)); return d;
}
__device__ __forceinline__ u64 add2(u64 a, u64 b) {
    u64 d; asm("add.rn.f32x2 %0,%1,%2;" : "=l"(d) : "l"(a), "l"(b)); return d;
}

// ---------------------------------------------------------------------------
// Kernel 0: precompute P[s][j] = psi_j(x_s) * x_s / sum_j psi_j(x_s),
// s = 1..100, x_s = fp32-iterated 0.99^s (matches reference's fp32 scan).
// ---------------------------------------------------------------------------
__global__ void init_table_kernel() {
    int s = threadIdx.x + 1;
    if (s > STEPS) return;
    float x = 1.0f;
    for (int i = 0; i < s; i++) x *= 0.99f;          // exact fp32 sequence
    const float n15 = 11.180339887498949f;           // 5^1.5 (A_X = 1)
    float psi[NBASIS], sum = 0.0f;
    #pragma unroll
    for (int j = 0; j < NBASIS; j++) {
        float c  = expf(-0.25f * (float)j);          // exp(-A_X * linspace)
        float s2 = n15 / c;
        float d  = x - c;
        psi[j] = expf(-0.5f * d * d / s2);
        sum += psi[j];
    }
    int base = (s - 1) * 12;
    #pragma unroll
    for (int j = 0; j < NBASIS; j++) {
        float p = psi[j] * x / sum;
        g_P[base + 2 * j]     = p;
        g_P[base + 2 * j + 1] = p;
    }
    g_P[base + 10] = 0.0f;
    g_P[base + 11] = 0.0f;
}

// ---------------------------------------------------------------------------
// Kernel 1: out42 = x @ W + b  (fp32, f32x2-packed over column pairs).
// One thread per batch row; W staged in smem padded to 44 cols so each
// column pair is a single LDS.64 (warp-uniform broadcast).
// ---------------------------------------------------------------------------
#define GEMM_TPB 128

__global__ __launch_bounds__(GEMM_TPB) void gemm_kernel(
    const float* __restrict__ x, const float* __restrict__ W,
    const float* __restrict__ b)
{
    __shared__ __align__(16) float Ws[KDIM * 44];
    for (int i = threadIdx.x; i < KDIM * OUTC; i += GEMM_TPB) {
        int k = i / OUTC, j = i - k * OUTC;
        Ws[k * 44 + j] = W[i];
    }
    for (int i = threadIdx.x; i < KDIM * 2; i += GEMM_TPB) {
        Ws[(i >> 1) * 44 + 42 + (i & 1)] = 0.0f;
    }
    __syncthreads();

    int row = blockIdx.x * GEMM_TPB + threadIdx.x;

    u64 acc[21];
    #pragma unroll
    for (int p = 0; p < 21; p++)
        acc[p] = pack2(__ldg(b + 2 * p), __ldg(b + 2 * p + 1));

    const float4* xr = (const float4*)(x + (size_t)row * KDIM);
    float4 cur = __ldg(xr);
    #pragma unroll 1
    for (int k4 = 0; k4 < KDIM / 4; k4++) {
        float4 nxt = cur;
        if (k4 < KDIM / 4 - 1) nxt = __ldg(xr + k4 + 1);
        float xs[4] = {cur.x, cur.y, cur.z, cur.w};
        #pragma unroll
        for (int q = 0; q < 4; q++) {
            int k = k4 * 4 + q;
            u64 xp = pack1(xs[q]);
            const u64* wrow = (const u64*)(Ws + k * 44);
            #pragma unroll
            for (int p = 0; p < 21; p++)
                acc[p] = fma2(xp, wrow[p], acc[p]);
        }
        cur = nxt;
    }

    u64* o = (u64*)g_out42 + (size_t)row * 21;
    #pragma unroll
    for (int p = 0; p < 21; p++) o[p] = acc[p];
}

// ---------------------------------------------------------------------------
// Kernel 2: DMP integration, 2 elements per thread (f32x2).
// dz = 56.25*(goal - y) - 15*z + fx,  fx = (w . P[s]) * (goal - y0)
// y += z*DT ; z += dz*DT ; emit y at steps 0,10,...,100.
// ---------------------------------------------------------------------------
#define DMP_TPB 256

__global__ __launch_bounds__(DMP_TPB) void dmp_kernel(
    const float* __restrict__ state, float* __restrict__ out)
{
    __shared__ __align__(16) float sP[STEPS * 12];
    for (int i = threadIdx.x; i < STEPS * 12; i += DMP_TPB) sP[i] = g_P[i];
    __syncthreads();

    int gid = blockIdx.x * DMP_TPB + threadIdx.x;
    int e0 = gid * 2;
    int b0 = e0 / DOF, d0 = e0 - b0 * DOF;
    int b1 = b0, d1 = d0 + 1;
    if (d1 == DOF) { d1 = 0; b1++; }

    const float* o0 = g_out42 + (size_t)b0 * OUTC;
    const float* o1 = g_out42 + (size_t)b1 * OUTC;
    float goal0 = o0[d0], goal1 = o1[d1];

    u64 w[NBASIS];
    #pragma unroll
    for (int j = 0; j < NBASIS; j++)
        w[j] = pack2(o0[DOF + NBASIS * d0 + j], o1[DOF + NBASIS * d1 + j]);

    u64 y = *(const u64*)(state + e0);   // e0 even -> 8B aligned
    float y00, y01; unpack2(y, y00, y01);
    u64 kp = pack2(goal0 - y00, goal1 - y01);
    u64 Cg = pack2(56.25f * goal0, 56.25f * goal1);
    u64 z  = pack1(0.05f);               // dy0 * TAU

    const u64 DTp = pack1(0.01f);
    const u64 nAZ = pack1(-15.0f);
    const u64 nC1 = pack1(-56.25f);

    float* w0p = out + (size_t)b0 * 77 + d0;
    float* w1p = out + (size_t)b1 * 77 + d1;
    w0p[0] = y00; w1p[0] = y01;

    #pragma unroll 1
    for (int tt = 1; tt <= 10; tt++) {
        #pragma unroll
        for (int ss = 0; ss < 10; ss++) {
            int idx = (tt - 1) * 10 + ss;
            const u64* P = (const u64*)(sP + idx * 12);
            u64 dot = mul2(P[0], w[0]);
            dot = fma2(P[1], w[1], dot);
            dot = fma2(P[2], w[2], dot);
            dot = fma2(P[3], w[3], dot);
            dot = fma2(P[4], w[4], dot);
            u64 fx = mul2(dot, kp);
            u64 a  = fma2(nC1, y, Cg);     // 56.25*goal - 56.25*y
            u64 t  = fma2(nAZ, z, fx);     // fx - 15*z
            u64 dz = add2(a, t);
            y = fma2(z,  DTp, y);          // uses old z
            z = fma2(dz, DTp, z);
        }
        float ya, yb; unpack2(y, ya, yb);
        w0p[tt * DOF] = ya;
        w1p[tt * DOF] = yb;
    }
}

// ---------------------------------------------------------------------------
extern "C" void kernel_launch(void* const* d_in, const int* in_sizes, int n_in,
                              void* d_out, int out_size)
{
    const float* x     = (const float*)d_in[0];
    const float* state = (const float*)d_in[1];
    const float* W     = (const float*)d_in[2];
    const float* b     = (const float*)d_in[3];
    float* out = (float*)d_out;

    init_table_kernel<<<1, 128>>>();
    gemm_kernel<<<BATCH / GEMM_TPB, GEMM_TPB>>>(x, W, b);
    dmp_kernel<<<(BATCH * DOF / 2) / DMP_TPB, DMP_TPB>>>(state, out);
}

// round 2
// speedup vs baseline: 1.1166x; 1.1166x over previous
#include <cuda_runtime.h>

#define BATCH   65536
#define DOF     7
#define NB      5
#define KDIM    256
#define OUTC    42
#define STEPS   100
#define TPB     128
#define RPB     128      // rows per block (== TPB, one row per thread)
#define GRID    (BATCH / RPB)

// dynamic smem layout (bytes)
#define WS_OFF   0
#define WS_BYTES (KDIM * 44 * 4)          // 45056, W padded to 44 cols (176B rows, 16B aligned)
#define SP_OFF   WS_BYTES                 // 45056
#define SP_BYTES (STEPS * 12 * 4)         // 4800, P table stride 48B (16B aligned)
#define EB_OFF   (SP_OFF + SP_BYTES)      // 49856
#define EB_BYTES (RPB * DOF * 4)          // 3584
#define SMEM_TOTAL (EB_OFF + EB_BYTES)    // 53440

typedef unsigned long long u64;
typedef unsigned int u32;

__device__ __forceinline__ u64 pack2(float a, float b) {
    u64 r; asm("mov.b64 %0,{%1,%2};" : "=l"(r) : "f"(a), "f"(b)); return r;
}
__device__ __forceinline__ u64 pack1(float a) { return pack2(a, a); }
__device__ __forceinline__ void unpack2(u64 v, float& a, float& b) {
    asm("mov.b64 {%0,%1},%2;" : "=f"(a), "=f"(b) : "l"(v));
}
__device__ __forceinline__ u64 fma2(u64 a, u64 b, u64 c) {
    u64 d; asm("fma.rn.f32x2 %0,%1,%2,%3;" : "=l"(d) : "l"(a), "l"(b), "l"(c)); return d;
}
__device__ __forceinline__ u64 mul2(u64 a, u64 b) {
    u64 d; asm("mul.rn.f32x2 %0,%1,%2;" : "=l"(d) : "l"(a), "l"(b)); return d;
}
__device__ __forceinline__ u64 add2(u64 a, u64 b) {
    u64 d; asm("add.rn.f32x2 %0,%1,%2;" : "=l"(d) : "l"(a), "l"(b)); return d;
}
__device__ __forceinline__ void lds_v2u64(u32 sa, u64& a, u64& b) {
    asm volatile("ld.shared.v2.b64 {%0,%1},[%2];" : "=l"(a), "=l"(b) : "r"(sa));
}
__device__ __forceinline__ u64 lds_u64(u32 sa) {
    u64 a; asm volatile("ld.shared.b64 %0,[%1];" : "=l"(a) : "r"(sa)); return a;
}

// ---------------------------------------------------------------------------
// Fused kernel: per-block W stage + RBF table, per-thread GEMM row (42 outs),
// then in-register DMP integration of that row's 7 DOFs, smem-staged emits.
// ---------------------------------------------------------------------------
__global__ __launch_bounds__(TPB, 4) void fused_kernel(
    const float* __restrict__ x, const float* __restrict__ state,
    const float* __restrict__ W, const float* __restrict__ bias,
    float* __restrict__ out)
{
    extern __shared__ __align__(16) char smem[];
    float* Ws   = (float*)(smem + WS_OFF);
    float* sP   = (float*)(smem + SP_OFF);
    float* ebuf = (float*)(smem + EB_OFF);

    const int tid = threadIdx.x;

    // ---- stage W (padded to 44 floats/row) ----
    #pragma unroll 4
    for (int i = tid; i < KDIM * OUTC; i += TPB) {
        int k = i / OUTC, j = i - k * OUTC;
        Ws[k * 44 + j] = __ldg(W + i);
    }
    for (int i = tid; i < KDIM * 2; i += TPB)
        Ws[(i >> 1) * 44 + OUTC + (i & 1)] = 0.0f;

    // ---- per-block RBF table: P[s][j] = psi_j(x_s)*x_s / sum_j psi_j ----
    if (tid < STEPS) {
        int s = tid + 1;
        float xv = 1.0f;
        for (int i = 0; i < s; i++) xv *= 0.99f;     // fp32 canonical-system scan
        const float n15 = 11.180339887498949f;        // 5^1.5
        float psi[NB], sum = 0.0f;
        #pragma unroll
        for (int j = 0; j < NB; j++) {
            float c  = expf(-0.25f * (float)j);
            float s2 = n15 / c;
            float d  = xv - c;
            psi[j] = expf(-0.5f * d * d / s2);
            sum += psi[j];
        }
        float inv = xv / sum;
        #pragma unroll
        for (int j = 0; j < NB; j++) {
            float p = psi[j] * inv;
            sP[tid * 12 + 2 * j]     = p;
            sP[tid * 12 + 2 * j + 1] = p;
        }
        sP[tid * 12 + 10] = 0.0f;
        sP[tid * 12 + 11] = 0.0f;
    }
    __syncthreads();

    // ---- GEMM phase: one row per thread, 21 f32x2 accumulators ----
    const int row = blockIdx.x * RPB + tid;

    u64 acc[21];
    #pragma unroll
    for (int p = 0; p < 21; p++)
        acc[p] = pack2(__ldg(bias + 2 * p), __ldg(bias + 2 * p + 1));

    const float4* xr = (const float4*)(x + (size_t)row * KDIM);
    float4 b0 = __ldg(xr + 0), b1 = __ldg(xr + 1);
    float4 b2 = __ldg(xr + 2), b3 = __ldg(xr + 3);

    const u32 wsbase = (u32)__cvta_generic_to_shared(Ws);

    #pragma unroll 1
    for (int it = 0; it < 16; it++) {
        float4 n0 = b0, n1 = b1, n2 = b2, n3 = b3;
        if (it < 15) {
            n0 = __ldg(xr + it * 4 + 4);
            n1 = __ldg(xr + it * 4 + 5);
            n2 = __ldg(xr + it * 4 + 6);
            n3 = __ldg(xr + it * 4 + 7);
        }
        float4 vv[4] = {b0, b1, b2, b3};
        #pragma unroll
        for (int u = 0; u < 4; u++) {
            float vals[4] = {vv[u].x, vv[u].y, vv[u].z, vv[u].w};
            #pragma unroll
            for (int q = 0; q < 4; q++) {
                int k = it * 16 + u * 4 + q;
                u32 sa = wsbase + k * 176;
                u64 xp = pack1(vals[q]);
                #pragma unroll
                for (int p = 0; p < 10; p++) {
                    u64 wa, wb;
                    lds_v2u64(sa + p * 16, wa, wb);
                    acc[2 * p]     = fma2(xp, wa, acc[2 * p]);
                    acc[2 * p + 1] = fma2(xp, wb, acc[2 * p + 1]);
                }
                acc[20] = fma2(xp, lds_u64(sa + 160), acc[20]);
            }
        }
        b0 = n0; b1 = n1; b2 = n2; b3 = n3;
    }

    // ---- unpack columns, build DOF-paired DMP state ----
    float cv[42];
    #pragma unroll
    for (int p = 0; p < 21; p++) unpack2(acc[p], cv[2 * p], cv[2 * p + 1]);

    u64 wp[4][NB];
    #pragma unroll
    for (int q = 0; q < 4; q++)
        #pragma unroll
        for (int j = 0; j < NB; j++) {
            float wlo = cv[DOF + 5 * (2 * q) + j];
            float whi = (q < 3) ? cv[DOF + 5 * (2 * q + 1) + j] : 0.0f;
            wp[q][j] = pack2(wlo, whi);
        }

    const float* sr = state + (size_t)row * DOF;
    float y0v[8];
    #pragma unroll
    for (int d = 0; d < DOF; d++) y0v[d] = __ldg(sr + d);
    y0v[7] = 0.0f;

    u64 y[4], z[4], kp[4], Cg[4];
    #pragma unroll
    for (int q = 0; q < 4; q++) {
        float g0 = cv[2 * q];
        float g1 = (q < 3) ? cv[2 * q + 1] : 0.0f;
        y[q]  = pack2(y0v[2 * q], y0v[2 * q + 1]);
        kp[q] = pack2(g0 - y0v[2 * q], g1 - y0v[2 * q + 1]);
        Cg[q] = pack2(56.25f * g0, 56.25f * g1);
        z[q]  = pack1(0.05f);
    }

    const u64 DTp = pack1(0.01f);
    const u64 nAZ = pack1(-15.0f);
    const u64 nC1 = pack1(-56.25f);
    const u32 pbase = (u32)__cvta_generic_to_shared(sP);

    // flush address precompute (independent of t)
    const size_t outbase = (size_t)blockIdx.x * RPB * 77;
    int fofs[7];
    #pragma unroll
    for (int r = 0; r < 7; r++) {
        int i = tid + r * TPB;
        int bb = i / 7, dd = i - bb * 7;
        fofs[r] = bb * 77 + dd;
    }

    // ---- emit t = 0 ----
    {
        #pragma unroll
        for (int q = 0; q < 4; q++) {
            float a, b; unpack2(y[q], a, b);
            ebuf[tid * 7 + 2 * q] = a;
            if (q < 3) ebuf[tid * 7 + 2 * q + 1] = b;
        }
        __syncthreads();
        #pragma unroll
        for (int r = 0; r < 7; r++)
            out[outbase + fofs[r]] = ebuf[tid + r * TPB];
        __syncthreads();
    }

    // ---- 100 integration steps, emit every 10 ----
    #pragma unroll 1
    for (int tt = 1; tt <= 10; tt++) {
        #pragma unroll
        for (int ss = 0; ss < 10; ss++) {
            int s = (tt - 1) * 10 + ss;
            u32 pa = pbase + s * 48;
            u64 P0, P1, P2, P3;
            lds_v2u64(pa,      P0, P1);
            lds_v2u64(pa + 16, P2, P3);
            u64 P4 = lds_u64(pa + 32);
            #pragma unroll
            for (int q = 0; q < 4; q++) {
                u64 dot = mul2(P0, wp[q][0]);
                dot = fma2(P1, wp[q][1], dot);
                dot = fma2(P2, wp[q][2], dot);
                dot = fma2(P3, wp[q][3], dot);
                dot = fma2(P4, wp[q][4], dot);
                u64 fx = mul2(dot, kp[q]);
                u64 a  = fma2(nC1, y[q], Cg[q]);   // 56.25*(goal - y)
                u64 t2 = fma2(nAZ, z[q], fx);      // fx - 15*z
                u64 dz = add2(a, t2);
                y[q] = fma2(z[q], DTp, y[q]);      // old z
                z[q] = fma2(dz,   DTp, z[q]);
            }
        }
        // emit
        #pragma unroll
        for (int q = 0; q < 4; q++) {
            float a, b; unpack2(y[q], a, b);
            ebuf[tid * 7 + 2 * q] = a;
            if (q < 3) ebuf[tid * 7 + 2 * q + 1] = b;
        }
        __syncthreads();
        #pragma unroll
        for (int r = 0; r < 7; r++)
            out[outbase + fofs[r] + tt * 7] = ebuf[tid + r * TPB];
        __syncthreads();
    }
}

// ---------------------------------------------------------------------------
extern "C" void kernel_launch(void* const* d_in, const int* in_sizes, int n_in,
                              void* d_out, int out_size)
{
    const float* x     = (const float*)d_in[0];
    const float* state = (const float*)d_in[1];
    const float* W     = (const float*)d_in[2];
    const float* b     = (const float*)d_in[3];
    float* out = (float*)d_out;

    cudaFuncSetAttribute(fused_kernel,
                         cudaFuncAttributeMaxDynamicSharedMemorySize, SMEM_TOTAL);
    fused_kernel<<<GRID, TPB, SMEM_TOTAL>>>(x, state, W, b, out);
}

// round 3
// speedup vs baseline: 1.1686x; 1.0466x over previous
#include <cuda_runtime.h>

#define DOF     7
#define NB      5
#define KDIM    256
#define OUTC    42
#define STEPS   100
#define TPB     256
#define RPB     128
#define BATCH   65536
#define GRID    (BATCH / RPB)        // 512
#define CK      32
#define NCHUNK  (KDIM / CK)          // 8
#define XPAD    34                   // xs row stride (floats)
#define WKP     258                  // Wt k stride (floats)

// ---- shared layout (float offsets) ----
#define WT_F    0
#define WT_SZ   (48 * WKP)           // 12384 floats (Wt; aliased by t48 later)
#define XS_F    WT_SZ
#define XS_SZ   (RPB * XPAD)         // 4352 floats (xs; aliased by ebuf+sP later)
#define SMEM_FLOATS (WT_SZ + XS_SZ)  // 16736 floats = 66944 bytes
#define T48P    132                  // t48 row stride (48 cols x 132)
#define EB_F    XS_F                 // emit buffer: 896 floats
#define SP_F    (XS_F + 1024)        // P table: 1200 floats (fits in 4352)

typedef unsigned long long u64;
typedef unsigned int u32;

__device__ __forceinline__ u64 pack2(float a, float b) {
    u64 r; asm("mov.b64 %0,{%1,%2};" : "=l"(r) : "f"(a), "f"(b)); return r;
}
__device__ __forceinline__ u64 pack1(float a) { return pack2(a, a); }
__device__ __forceinline__ void unpack2(u64 v, float& a, float& b) {
    asm("mov.b64 {%0,%1},%2;" : "=f"(a), "=f"(b) : "l"(v));
}
__device__ __forceinline__ u64 fma2(u64 a, u64 b, u64 c) {
    u64 d; asm("fma.rn.f32x2 %0,%1,%2,%3;" : "=l"(d) : "l"(a), "l"(b), "l"(c)); return d;
}
__device__ __forceinline__ u64 mul2(u64 a, u64 b) {
    u64 d; asm("mul.rn.f32x2 %0,%1,%2;" : "=l"(d) : "l"(a), "l"(b)); return d;
}
__device__ __forceinline__ u64 add2(u64 a, u64 b) {
    u64 d; asm("add.rn.f32x2 %0,%1,%2;" : "=l"(d) : "l"(a), "l"(b)); return d;
}
__device__ __forceinline__ void lds_v2u64(u32 sa, u64& a, u64& b) {
    asm volatile("ld.shared.v2.b64 {%0,%1},[%2];" : "=l"(a), "=l"(b) : "r"(sa));
}
__device__ __forceinline__ u64 lds_u64(u32 sa) {
    u64 a; asm volatile("ld.shared.b64 %0,[%1];" : "=l"(a) : "r"(sa)); return a;
}
__device__ __forceinline__ void sts_u64(u32 sa, u64 v) {
    asm volatile("st.shared.b64 [%0],%1;" :: "r"(sa), "l"(v));
}

__global__ __launch_bounds__(TPB, 2) void fused_kernel(
    const float* __restrict__ x, const float* __restrict__ state,
    const float* __restrict__ W, const float* __restrict__ bias,
    float* __restrict__ out)
{
    extern __shared__ __align__(16) float sm[];
    float* Wt   = sm + WT_F;     // [48][WKP] transposed W, k contiguous
    float* xs   = sm + XS_F;     // [128][XPAD] row-major x chunk
    float* t48  = sm + 0;        // [48][T48P] handoff (aliases Wt)
    float* ebuf = sm + EB_F;     // [128][7]  emit stage (aliases xs)
    float* sP   = sm + SP_F;     // [100][12] RBF table (aliases xs)

    const int tid = threadIdx.x;

    // ---- prefetch x chunk 0 (each thread: 16 floats of one row) ----
    const int lr = tid & 127, ks = tid >> 7;
    const float4* xsrc = (const float4*)(x + ((size_t)(blockIdx.x * RPB + lr)) * KDIM) + ks * 4;
    float4 pf0 = __ldg(xsrc + 0), pf1 = __ldg(xsrc + 1);
    float4 pf2 = __ldg(xsrc + 2), pf3 = __ldg(xsrc + 3);

    // ---- stage W transposed: Wt[col][k], pad cols 42..47 = 0 ----
    #pragma unroll 4
    for (int i = tid; i < KDIM * OUTC; i += TPB) {
        int k = i / OUTC, c = i - k * OUTC;
        Wt[c * WKP + k] = __ldg(W + i);
    }
    for (int i = tid; i < 6 * WKP; i += TPB)
        Wt[OUTC * WKP + i] = 0.0f;

    // ---- GEMM: k-packed f32x2, thread tile 4 rows x 6 cols ----
    const int rg = tid & 31;          // row base (rows rg + 32p)
    const int cg = tid >> 5;          // col group (cols cg*6 .. cg*6+5); warp-uniform
    const u32 xb = (u32)__cvta_generic_to_shared(xs);
    const u32 wb = (u32)__cvta_generic_to_shared(Wt) + (u32)(cg * 6 * WKP) * 4u;

    u64 acc[4][6];
    #pragma unroll
    for (int p = 0; p < 4; p++)
        #pragma unroll
        for (int c = 0; c < 6; c++) acc[p][c] = 0ull;

    #pragma unroll 1
    for (int ch = 0; ch < NCHUNK; ch++) {
        // store prefetched chunk: xs[lr][ks*16 + 0..15]
        {
            u32 sa = xb + (u32)(lr * XPAD + ks * 16) * 4u;
            sts_u64(sa +  0, pack2(pf0.x, pf0.y)); sts_u64(sa +  8, pack2(pf0.z, pf0.w));
            sts_u64(sa + 16, pack2(pf1.x, pf1.y)); sts_u64(sa + 24, pack2(pf1.z, pf1.w));
            sts_u64(sa + 32, pack2(pf2.x, pf2.y)); sts_u64(sa + 40, pack2(pf2.z, pf2.w));
            sts_u64(sa + 48, pack2(pf3.x, pf3.y)); sts_u64(sa + 56, pack2(pf3.z, pf3.w));
        }
        __syncthreads();
        if (ch < NCHUNK - 1) {
            const float4* nx = xsrc + (ch + 1) * 8;
            pf0 = __ldg(nx + 0); pf1 = __ldg(nx + 1);
            pf2 = __ldg(nx + 2); pf3 = __ldg(nx + 3);
        }
        const u32 wk = wb + (u32)(ch * CK) * 4u;
        #pragma unroll
        for (int kp = 0; kp < CK / 2; kp++) {
            u64 wv[6];
            #pragma unroll
            for (int c = 0; c < 6; c++)
                wv[c] = lds_u64(wk + (u32)(c * WKP + 2 * kp) * 4u);
            u64 xv[4];
            #pragma unroll
            for (int p = 0; p < 4; p++)
                xv[p] = lds_u64(xb + (u32)((rg + 32 * p) * XPAD + 2 * kp) * 4u);
            #pragma unroll
            for (int p = 0; p < 4; p++)
                #pragma unroll
                for (int c = 0; c < 6; c++)
                    acc[p][c] = fma2(xv[p], wv[c], acc[p][c]);
        }
        __syncthreads();   // xs reads done before next overwrite; Wt free after last
    }

    // ---- horizontal sum + bias -> t48[col][row] (aliases Wt; loop ended with sync) ----
    #pragma unroll
    for (int c = 0; c < 6; c++) {
        int col = cg * 6 + c;
        if (col < OUTC) {
            float bv = __ldg(bias + col);
            #pragma unroll
            for (int p = 0; p < 4; p++) {
                float lo, hi; unpack2(acc[p][c], lo, hi);
                t48[col * T48P + (rg + 32 * p)] = lo + hi + bv;
            }
        }
    }

    // ---- RBF table: P[s][j] = psi_j(x_s)*x_s/sum psi (duplicated pairs) ----
    if (tid < STEPS) {
        int s = tid + 1;
        float xv = 1.0f;
        for (int i = 0; i < s; i++) xv *= 0.99f;       // fp32 canonical scan
        const float n15 = 11.180339887498949f;          // 5^1.5
        float psi[NB], sum = 0.0f;
        #pragma unroll
        for (int j = 0; j < NB; j++) {
            float c  = expf(-0.25f * (float)j);
            float s2 = n15 / c;
            float d  = xv - c;
            psi[j] = expf(-0.5f * d * d / s2);
            sum += psi[j];
        }
        float inv = xv / sum;
        #pragma unroll
        for (int j = 0; j < NB; j++) {
            float p = psi[j] * inv;
            sP[tid * 12 + 2 * j]     = p;
            sP[tid * 12 + 2 * j + 1] = p;
        }
        sP[tid * 12 + 10] = 0.0f;
        sP[tid * 12 + 11] = 0.0f;
    }
    __syncthreads();

    // ---- DMP: 2 threads per row; half 0 -> DOFs 0..3, half 1 -> DOFs 4..6 ----
    const int row  = tid & 127;
    const int half = tid >> 7;
    const int base = half * 4;
    const int nv   = half ? 3 : 4;

    float g[4], wsc[4][NB], y0v[4];
    #pragma unroll
    for (int j = 0; j < 4; j++) {
        bool v = (j < nv);
        g[j]   = v ? t48[(base + j) * T48P + row] : 0.0f;
        #pragma unroll
        for (int n = 0; n < NB; n++)
            wsc[j][n] = v ? t48[(DOF + (base + j) * NB + n) * T48P + row] : 0.0f;
        y0v[j] = v ? __ldg(state + ((size_t)(blockIdx.x * RPB + row)) * DOF + base + j) : 0.0f;
    }

    u64 wq[2][NB], y[2], z[2], kp2[2], Cg[2];
    #pragma unroll
    for (int q = 0; q < 2; q++) {
        int j0 = 2 * q, j1 = 2 * q + 1;
        #pragma unroll
        for (int n = 0; n < NB; n++) wq[q][n] = pack2(wsc[j0][n], wsc[j1][n]);
        y[q]   = pack2(y0v[j0], y0v[j1]);
        kp2[q] = pack2(g[j0] - y0v[j0], g[j1] - y0v[j1]);
        Cg[q]  = pack2(56.25f * g[j0], 56.25f * g[j1]);
        z[q]   = pack1(0.05f);
    }

    const u64 DTp = pack1(0.01f);
    const u64 nAZ = pack1(-15.0f);
    const u64 nC1 = pack1(-56.25f);
    const u32 spb = (u32)__cvta_generic_to_shared(sP);

    // flush index precompute
    int fb[4], fd[4];
    #pragma unroll
    for (int r = 0; r < 4; r++) {
        int i = tid + r * TPB;
        fb[r] = i / 7; fd[r] = i - 7 * fb[r];
    }
    const size_t ob = (size_t)blockIdx.x * RPB * 77;

    // emit t = 0
    #pragma unroll
    for (int j = 0; j < 4; j++)
        if (j < nv) ebuf[row * 7 + base + j] = y0v[j];
    __syncthreads();
    #pragma unroll
    for (int r = 0; r < 4; r++) {
        int i = tid + r * TPB;
        if (i < RPB * 7) out[ob + (size_t)fb[r] * 77 + fd[r]] = ebuf[i];
    }
    __syncthreads();

    // 100 steps, emit every 10
    #pragma unroll 1
    for (int tt = 1; tt <= 10; tt++) {
        #pragma unroll
        for (int ss = 0; ss < 10; ss++) {
            int s = (tt - 1) * 10 + ss;
            u32 pa = spb + (u32)s * 48u;
            u64 P0, P1, P2, P3;
            lds_v2u64(pa,      P0, P1);
            lds_v2u64(pa + 16, P2, P3);
            u64 P4 = lds_u64(pa + 32);
            #pragma unroll
            for (int q = 0; q < 2; q++) {
                u64 dot = mul2(P0, wq[q][0]);
                dot = fma2(P1, wq[q][1], dot);
                dot = fma2(P2, wq[q][2], dot);
                dot = fma2(P3, wq[q][3], dot);
                dot = fma2(P4, wq[q][4], dot);
                u64 fx = mul2(dot, kp2[q]);
                u64 a  = fma2(nC1, y[q], Cg[q]);   // 56.25*(goal - y)
                u64 t2 = fma2(nAZ, z[q], fx);      // fx - 15*z
                u64 dz = add2(a, t2);
                y[q] = fma2(z[q], DTp, y[q]);      // uses old z
                z[q] = fma2(dz,   DTp, z[q]);
            }
        }
        #pragma unroll
        for (int q = 0; q < 2; q++) {
            float a, b; unpack2(y[q], a, b);
            int j0 = 2 * q;
            if (j0     < nv) ebuf[row * 7 + base + j0]     = a;
            if (j0 + 1 < nv) ebuf[row * 7 + base + j0 + 1] = b;
        }
        __syncthreads();
        #pragma unroll
        for (int r = 0; r < 4; r++) {
            int i = tid + r * TPB;
            if (i < RPB * 7) out[ob + (size_t)fb[r] * 77 + (size_t)tt * 7 + fd[r]] = ebuf[i];
        }
        __syncthreads();
    }
}

// ---------------------------------------------------------------------------
extern "C" void kernel_launch(void* const* d_in, const int* in_sizes, int n_in,
                              void* d_out, int out_size)
{
    const float* x     = (const float*)d_in[0];
    const float* state = (const float*)d_in[1];
    const float* W     = (const float*)d_in[2];
    const float* b     = (const float*)d_in[3];
    float* out = (float*)d_out;

    cudaFuncSetAttribute(fused_kernel,
                         cudaFuncAttributeMaxDynamicSharedMemorySize,
                         SMEM_FLOATS * (int)sizeof(float));
    fused_kernel<<<GRID, TPB, SMEM_FLOATS * sizeof(float)>>>(x, state, W, b, out);
}

// round 4
// speedup vs baseline: 1.5935x; 1.3636x over previous
#include <cuda_runtime.h>
#include <math.h>

#define DOF     7
#define NB      5
#define KDIM    256
#define OUTC    42
#define STEPS   100
#define TPB     256
#define RPB     128
#define BATCH   65536
#define GRID    (BATCH / RPB)        // 512
#define CK      32
#define NCHUNK  (KDIM / CK)          // 8
#define XPAD    36                   // xs row stride (floats), 144B: 16B-aligned, conflict-free
#define WKP     260                  // Wt k stride (floats), 1040B: 16B-aligned

// ---- shared layout (float offsets) ----
#define WT_F    0
#define WT_SZ   (48 * WKP)           // 12480
#define XS0_F   WT_SZ                // 12480
#define XS1_F   (XS0_F + RPB * XPAD) // 17088
#define SMEM_FLOATS (XS1_F + RPB * XPAD)  // 21696 floats = 86784 B
// aliases after GEMM:
#define T48P    132
#define T48_F   0                    // 48*132 = 6336 floats
#define EB2_F   6336                 // 128*77 = 9856 floats, ends 16192 < 21696

typedef unsigned long long u64;
typedef unsigned int u32;

// Linear DMP map: y[t] = A[t]·[y0, g, u0..u4, 1],  u_j = (g-y0)*w_j.
// Stored as duplicated f32 pairs for direct u64 (f32x2) constant loads.
__constant__ __align__(16) float c_A2[11 * 16];

__device__ __forceinline__ u64 pack2(float a, float b) {
    u64 r; asm("mov.b64 %0,{%1,%2};" : "=l"(r) : "f"(a), "f"(b)); return r;
}
__device__ __forceinline__ void unpack2(u64 v, float& a, float& b) {
    asm("mov.b64 {%0,%1},%2;" : "=f"(a), "=f"(b) : "l"(v));
}
__device__ __forceinline__ u64 fma2(u64 a, u64 b, u64 c) {
    u64 d; asm("fma.rn.f32x2 %0,%1,%2,%3;" : "=l"(d) : "l"(a), "l"(b), "l"(c)); return d;
}
__device__ __forceinline__ void lds_v2u64(u32 sa, u64& a, u64& b) {
    asm volatile("ld.shared.v2.b64 {%0,%1},[%2];" : "=l"(a), "=l"(b) : "r"(sa));
}
__device__ __forceinline__ void cp_async16(u32 dst, const float* src) {
    asm volatile("cp.async.cg.shared.global [%0],[%1],16;" :: "r"(dst), "l"(src));
}
#define CP_COMMIT() asm volatile("cp.async.commit_group;")
#define CP_WAIT0()  asm volatile("cp.async.wait_group 0;")

__global__ __launch_bounds__(TPB, 2) void fused_kernel(
    const float* __restrict__ x, const float* __restrict__ state,
    const float* __restrict__ W, const float* __restrict__ bias,
    float* __restrict__ out)
{
    extern __shared__ __align__(16) float sm[];
    float* Wt  = sm + WT_F;
    float* t48 = sm + T48_F;
    float* eb2 = sm + EB2_F;

    const int tid = threadIdx.x;
    const int lr = tid & 127, ks = tid >> 7;   // copy map: row, 16-float half
    const u32 xs0 = (u32)__cvta_generic_to_shared(sm + XS0_F);
    const u32 xs1 = (u32)__cvta_generic_to_shared(sm + XS1_F);
    const float* xrow = x + ((size_t)(blockIdx.x * RPB + lr)) * KDIM + ks * 16;
    const u32 xdst_off = (u32)(lr * XPAD + ks * 16) * 4u;

    // issue chunk 0 copy immediately
    {
        u32 d = xs0 + xdst_off;
        cp_async16(d, xrow);          cp_async16(d + 16, xrow + 4);
        cp_async16(d + 32, xrow + 8); cp_async16(d + 48, xrow + 12);
        CP_COMMIT();
    }

    // ---- stage W transposed: Wt[col][k]; pad cols 42..47 = 0 ----
    #pragma unroll 4
    for (int i = tid; i < KDIM * OUTC; i += TPB) {
        int k = i / OUTC, c = i - k * OUTC;
        Wt[c * WKP + k] = __ldg(W + i);
    }
    for (int i = tid; i < 6 * WKP; i += TPB)
        Wt[OUTC * WKP + i] = 0.0f;

    // ---- GEMM: k-packed f32x2, thread tile 4 rows x 6 cols, cp.async pipeline ----
    const int rg = tid & 31;          // lane -> row base
    const int cg = tid >> 5;          // warp -> col group (warp-uniform)
    const u32 wb = (u32)__cvta_generic_to_shared(Wt) + (u32)(cg * 6 * WKP) * 4u;

    u64 acc[4][6];
    #pragma unroll
    for (int p = 0; p < 4; p++)
        #pragma unroll
        for (int c = 0; c < 6; c++) acc[p][c] = 0ull;

    #pragma unroll 1
    for (int ch = 0; ch < NCHUNK; ch++) {
        CP_WAIT0();                   // own copies of chunk ch landed
        __syncthreads();              // all copies visible; prior compute done
        if (ch < NCHUNK - 1) {        // overlap next copy with this compute
            u32 d = ((ch + 1) & 1 ? xs1 : xs0) + xdst_off;
            const float* s = xrow + (ch + 1) * CK;
            cp_async16(d, s);          cp_async16(d + 16, s + 4);
            cp_async16(d + 32, s + 8); cp_async16(d + 48, s + 12);
            CP_COMMIT();
        }
        const u32 xb = (ch & 1) ? xs1 : xs0;
        const u32 wk = wb + (u32)(ch * CK) * 4u;
        #pragma unroll
        for (int kq = 0; kq < CK / 4; kq++) {      // 4 k per iteration
            u64 wva[6], wvb[6];
            #pragma unroll
            for (int c = 0; c < 6; c++)
                lds_v2u64(wk + (u32)(c * WKP) * 4u + (u32)kq * 16u, wva[c], wvb[c]);
            u64 xva[4], xvb[4];
            #pragma unroll
            for (int p = 0; p < 4; p++)
                lds_v2u64(xb + (u32)((rg + 32 * p) * XPAD) * 4u + (u32)kq * 16u,
                          xva[p], xvb[p]);
            #pragma unroll
            for (int p = 0; p < 4; p++)
                #pragma unroll
                for (int c = 0; c < 6; c++) {
                    acc[p][c] = fma2(xva[p], wva[c], acc[p][c]);
                    acc[p][c] = fma2(xvb[p], wvb[c], acc[p][c]);
                }
        }
    }
    __syncthreads();   // Wt/xs reads done before t48 overwrite

    // ---- horizontal sum + bias -> t48[col][row] (aliases Wt) ----
    #pragma unroll
    for (int c = 0; c < 6; c++) {
        int col = cg * 6 + c;
        if (col < OUTC) {
            float bv = __ldg(bias + col);
            #pragma unroll
            for (int p = 0; p < 4; p++) {
                float lo, hi; unpack2(acc[p][c], lo, hi);
                t48[col * T48P + (rg + 32 * p)] = lo + hi + bv;
            }
        }
    }
    __syncthreads();

    // ---- linear DMP: y[t] = A[t]·[y0, g, u, 1]; 2 threads per row ----
    const int row  = tid & 127;
    const int half = tid >> 7;
    const int base = half * 4;
    const int nv   = half ? 3 : 4;

    float gv[4], wv5[4][NB], y0v[4];
    #pragma unroll
    for (int j = 0; j < 4; j++) {
        bool ok = (j < nv);
        int dof = base + j;
        gv[j] = ok ? t48[dof * T48P + row] : 0.0f;
        #pragma unroll
        for (int n = 0; n < NB; n++)
            wv5[j][n] = ok ? t48[(DOF + dof * NB + n) * T48P + row] : 0.0f;
        y0v[j] = ok ? __ldg(state + ((size_t)(blockIdx.x * RPB + row)) * DOF + dof)
                    : 0.0f;
    }

    u64 Y0[2], Gp[2], U[2][NB];
    #pragma unroll
    for (int q = 0; q < 2; q++) {
        int j0 = 2 * q, j1 = 2 * q + 1;
        float k0 = gv[j0] - y0v[j0], k1 = gv[j1] - y0v[j1];
        Y0[q] = pack2(y0v[j0], y0v[j1]);
        Gp[q] = pack2(gv[j0], gv[j1]);
        #pragma unroll
        for (int n = 0; n < NB; n++)
            U[q][n] = pack2(k0 * wv5[j0][n], k1 * wv5[j1][n]);
    }

    #pragma unroll
    for (int t = 0; t < 11; t++) {
        const u64* Ar = (const u64*)(c_A2 + t * 16);
        u64 a0 = Ar[0], a1 = Ar[1], a2 = Ar[2], a3 = Ar[3];
        u64 a4 = Ar[4], a5 = Ar[5], a6 = Ar[6], a7 = Ar[7];
        #pragma unroll
        for (int q = 0; q < 2; q++) {
            u64 r = fma2(a0, Y0[q], a7);
            r = fma2(a1, Gp[q], r);
            r = fma2(a2, U[q][0], r);
            r = fma2(a3, U[q][1], r);
            r = fma2(a4, U[q][2], r);
            r = fma2(a5, U[q][3], r);
            r = fma2(a6, U[q][4], r);
            float lo, hi; unpack2(r, lo, hi);
            int j0 = 2 * q;
            if (j0     < nv) eb2[row * 77 + t * 7 + base + j0]     = lo;
            if (j0 + 1 < nv) eb2[row * 77 + t * 7 + base + j0 + 1] = hi;
        }
    }
    __syncthreads();

    // ---- single fully-coalesced output copy: 9856 floats = 2464 float4 ----
    const float4* s4 = (const float4*)eb2;
    float4* d4 = (float4*)(out + (size_t)blockIdx.x * RPB * 77);
    #pragma unroll 1
    for (int i = tid; i < (RPB * 77) / 4; i += TPB) d4[i] = s4[i];
}

// ---------------------------------------------------------------------------
// Host: precompute the linear DMP map A (8 basis runs of the fp32 recursion).
// ---------------------------------------------------------------------------
static float hA2[11 * 16];

static void compute_A_host() {
    float c[NB], s2[NB], P[STEPS][NB];
    const float n15 = 11.180339887498949f;   // 5^1.5
    for (int j = 0; j < NB; j++) {
        c[j]  = expf(-0.25f * (float)j);
        s2[j] = n15 / c[j];
    }
    float xv = 1.0f;
    for (int s = 0; s < STEPS; s++) {
        xv = xv - xv * 0.01f;                 // canonical system (fp32)
        float sum = 0.0f, psi[NB];
        for (int j = 0; j < NB; j++) {
            float d = xv - c[j];
            psi[j] = expf(-0.5f * d * d / s2[j]);
            sum += psi[j];
        }
        for (int j = 0; j < NB; j++) P[s][j] = psi[j] * xv / sum;
    }
    // basis order: 0:y0, 1:g, 2..6:u0..u4, 7:const(z0=0.05)
    for (int b = 0; b < 8; b++) {
        float y0b = (b == 0) ? 1.0f : 0.0f;
        float gb  = (b == 1) ? 1.0f : 0.0f;
        float u[NB];
        for (int j = 0; j < NB; j++) u[j] = (b == 2 + j) ? 1.0f : 0.0f;
        float y = y0b;
        float z = (b == 7) ? 0.05f : 0.0f;
        hA2[0 * 16 + 2 * b] = hA2[0 * 16 + 2 * b + 1] = y;
        int s = 0;
        for (int tt = 1; tt <= 10; tt++) {
            for (int ss = 0; ss < 10; ss++, s++) {
                float fx = 0.0f;
                for (int j = 0; j < NB; j++) fx += P[s][j] * u[j];
                float dz = 56.25f * (gb - y) - 15.0f * z + fx;
                y = y + z * 0.01f;            // uses old z
                z = z + dz * 0.01f;
            }
            hA2[tt * 16 + 2 * b] = hA2[tt * 16 + 2 * b + 1] = y;
        }
    }
}

extern "C" void kernel_launch(void* const* d_in, const int* in_sizes, int n_in,
                              void* d_out, int out_size)
{
    const float* x     = (const float*)d_in[0];
    const float* state = (const float*)d_in[1];
    const float* W     = (const float*)d_in[2];
    const float* b     = (const float*)d_in[3];
    float* out = (float*)d_out;

    compute_A_host();   // deterministic, same every call
    cudaMemcpyToSymbolAsync(c_A2, hA2, sizeof(hA2), 0, cudaMemcpyHostToDevice);

    cudaFuncSetAttribute(fused_kernel,
                         cudaFuncAttributeMaxDynamicSharedMemorySize,
                         SMEM_FLOATS * (int)sizeof(float));
    fused_kernel<<<GRID, TPB, SMEM_FLOATS * sizeof(float)>>>(x, state, W, b, out);
}

// round 6
// speedup vs baseline: 2.4649x; 1.5468x over previous
#include <cuda_runtime.h>
#include <cuda_bf16.h>
#include <math.h>

typedef unsigned int u32;

#define DOF   7
#define NB    5
#define KDIM  256
#define OUTC  42
#define RPB   128
#define BATCH 65536
#define GRID  (BATCH / RPB)   // 512
#define TPB   512

// ---- smem layout (bytes). Row stride 528 B = 264 halves: 16B-aligned and
// LDSM-conflict-free (132 words % 32 == 4 -> 8 rows hit distinct bank groups).
#define AST    528
#define A_HI   0                    // 128 x 528 = 67584
#define A_LO   67584
#define B_HI   135168               // 48 x 528 = 25344
#define B_LO   160512
#define BIAS_B 185856               // 48 floats
#define SMEM_TOTAL 186112
// epilogue aliases (A tiles dead after MMA):
#define CS0    0                    // 128*50*4 = 25600 (K-half 0 partials)
#define CS1    25600                // K-half 1 partials
#define EB     51200                // 128*77*4 = 39424 -> ends 90624

// DMP linear map: y[t] = A[t] . [y0, g, u0..u4, 1]
__constant__ float c_A[11 * 8];

__device__ __forceinline__ u32 sm2u32(const void* p) {
    u32 a; asm("{.reg .u64 t; cvta.to.shared.u64 t,%1; cvt.u32.u64 %0,t;}"
               : "=r"(a) : "l"(p));
    return a;
}
__device__ __forceinline__ void ldsm4(u32 addr, u32& r0, u32& r1, u32& r2, u32& r3) {
    asm volatile("ldmatrix.sync.aligned.m8n8.x4.shared.b16 {%0,%1,%2,%3},[%4];"
                 : "=r"(r0), "=r"(r1), "=r"(r2), "=r"(r3) : "r"(addr));
}
__device__ __forceinline__ void mma16816(float* c, const u32* a, u32 b0, u32 b1) {
    asm volatile(
        "mma.sync.aligned.m16n8k16.row.col.f32.bf16.bf16.f32 "
        "{%0,%1,%2,%3},{%4,%5,%6,%7},{%8,%9},{%0,%1,%2,%3};"
        : "+f"(c[0]), "+f"(c[1]), "+f"(c[2]), "+f"(c[3])
        : "r"(a[0]), "r"(a[1]), "r"(a[2]), "r"(a[3]), "r"(b0), "r"(b1));
}

__global__ __launch_bounds__(TPB, 1)
void fused_kernel(const float* __restrict__ x, const float* __restrict__ state,
                  const float* __restrict__ W, const float* __restrict__ bias,
                  float* __restrict__ out)
{
    extern __shared__ __align__(1024) char sm[];
    const u32 smb = sm2u32(sm);
    const int tid = threadIdx.x;
    const int wid = tid >> 5;
    const int lane = tid & 31;
    float* biass = (float*)(sm + BIAS_B);

    // ---- stage bias, zero B pad rows 42..47 ----
    if (tid < 48) biass[tid] = (tid < OUTC) ? __ldg(bias + tid) : 0.0f;
    for (int i = tid; i < (6 * AST) / 4; i += TPB) {
        *(u32*)(sm + B_HI + OUTC * AST + 4 * i) = 0;
        *(u32*)(sm + B_LO + OUTC * AST + 4 * i) = 0;
    }

    // ---- W -> bf16 hi/lo, transposed: Wt[n][k] ----
    for (int i = tid; i < KDIM * OUTC; i += TPB) {
        int k = i / OUTC, n = i - k * OUTC;
        float w = __ldg(W + i);
        u32 uw = __float_as_uint(w);
        float hw = __uint_as_float(uw & 0xFFFF0000u);
        __nv_bfloat16 lw = __float2bfloat16(w - hw);
        u32 off = (u32)(n * AST + k * 2);
        *(unsigned short*)(sm + B_HI + off) = (unsigned short)(uw >> 16);
        *(unsigned short*)(sm + B_LO + off) = *(const unsigned short*)&lw;
    }

    // ---- x -> bf16 hi/lo, row-major A[r][k]; fully coalesced LDG ----
    const float4* xsrc = (const float4*)(x + (size_t)blockIdx.x * RPB * KDIM);
    #pragma unroll 4
    for (int j = 0; j < (RPB * KDIM / 4) / TPB; j++) {
        int idx = tid + j * TPB;
        int r = idx >> 6, k4 = idx & 63;
        float4 v = __ldg(xsrc + idx);
        u32 ux = __float_as_uint(v.x), uy = __float_as_uint(v.y);
        u32 uz = __float_as_uint(v.z), uw2 = __float_as_uint(v.w);
        u32 hi01 = __byte_perm(ux, uy, 0x7632);
        u32 hi23 = __byte_perm(uz, uw2, 0x7632);
        float lx = v.x - __uint_as_float(ux & 0xFFFF0000u);
        float ly = v.y - __uint_as_float(uy & 0xFFFF0000u);
        float lz = v.z - __uint_as_float(uz & 0xFFFF0000u);
        float lw2 = v.w - __uint_as_float(uw2 & 0xFFFF0000u);
        u32 lo01, lo23;
        asm("cvt.rn.bf16x2.f32 %0,%1,%2;" : "=r"(lo01) : "f"(ly), "f"(lx));
        asm("cvt.rn.bf16x2.f32 %0,%1,%2;" : "=r"(lo23) : "f"(lw2), "f"(lz));
        u32 off = (u32)(r * AST + k4 * 8);
        *(uint2*)(sm + A_HI + off) = make_uint2(hi01, hi23);
        *(uint2*)(sm + A_LO + off) = make_uint2(lo01, lo23);
    }
    __syncthreads();

    // ---- MMA: 16 warps = 8 m-tiles x 2 k-halves; 3 passes hi*hi + hi*lo + lo*hi ----
    const int mw = wid & 7;            // m-tile (rows mw*16..+15)
    const int ksel = wid >> 3;         // k-half
    // A ldmatrix.x4 lane address: m0/m1 = rows 0-15 khalf0(of step), m2/m3 = rows 0-15 k+8
    const u32 arow = (u32)((mw * 16 + (lane & 15)) * AST + (lane >> 4) * 16);
    // B ldmatrix.x4: m0/m1 = n-rows 0-7 (k0, k8), m2/m3 = n-rows 8-15 (k0, k8)
    const u32 brow = (u32)((((lane & 7) | ((lane >> 4) << 3))) * AST + ((lane >> 3) & 1) * 16);
    const u32 aHi = smb + A_HI + arow + (u32)ksel * 256;
    const u32 aLo = smb + A_LO + arow + (u32)ksel * 256;
    const u32 bHi = smb + B_HI + brow + (u32)ksel * 256;
    const u32 bLo = smb + B_LO + brow + (u32)ksel * 256;

    float c[6][4];
    #pragma unroll
    for (int n = 0; n < 6; n++)
        #pragma unroll
        for (int q = 0; q < 4; q++) c[n][q] = 0.0f;

    #pragma unroll 2
    for (int s = 0; s < 8; s++) {      // 8 k16-steps per k-half
        u32 ah[4], al[4], bh[12], bl[12];
        ldsm4(aHi + s * 32, ah[0], ah[1], ah[2], ah[3]);
        ldsm4(aLo + s * 32, al[0], al[1], al[2], al[3]);
        #pragma unroll
        for (int nt = 0; nt < 3; nt++) {
            ldsm4(bHi + nt * (16 * AST) + s * 32,
                  bh[nt * 4], bh[nt * 4 + 1], bh[nt * 4 + 2], bh[nt * 4 + 3]);
            ldsm4(bLo + nt * (16 * AST) + s * 32,
                  bl[nt * 4], bl[nt * 4 + 1], bl[nt * 4 + 2], bl[nt * 4 + 3]);
        }
        #pragma unroll
        for (int n = 0; n < 6; n++) {
            int bi = (n >> 1) * 4 + (n & 1) * 2;
            mma16816(c[n], ah, bh[bi], bh[bi + 1]);   // hi*hi
            mma16816(c[n], ah, bl[bi], bl[bi + 1]);   // hi*lo
            mma16816(c[n], al, bh[bi], bh[bi + 1]);   // lo*hi
        }
    }
    __syncthreads();   // all A/B reads done before cs overwrites A_HI

    // ---- stage C partials: cs[ksel][row][col], row stride 50 floats ----
    {
        float* cs = (float*)(sm + (ksel ? CS1 : CS0));
        int r0 = mw * 16 + (lane >> 2);
        int c0 = 2 * (lane & 3);
        #pragma unroll
        for (int n = 0; n < 6; n++) {
            int col = n * 8 + c0;
            *(float2*)&cs[r0 * 50 + col]       = make_float2(c[n][0], c[n][1]);
            *(float2*)&cs[(r0 + 8) * 50 + col] = make_float2(c[n][2], c[n][3]);
        }
    }
    __syncthreads();

    // ---- epilogue: linear DMP map, one thread per batch row ----
    if (tid < RPB) {
        const float* cs0 = (const float*)(sm + CS0) + tid * 50;
        const float* cs1 = (const float*)(sm + CS1) + tid * 50;
        float* eb = (float*)(sm + EB) + tid * 77;
        const float* st = state + ((size_t)(blockIdx.x * RPB + tid)) * DOF;

        float g[DOF], y0v[DOF], ku[DOF], wv[DOF][NB];
        #pragma unroll
        for (int d = 0; d < DOF; d++) {
            y0v[d] = __ldg(st + d);
            g[d]   = cs0[d] + cs1[d] + biass[d];
            ku[d]  = g[d] - y0v[d];
            #pragma unroll
            for (int j = 0; j < NB; j++) {
                int col = DOF + 5 * d + j;
                wv[d][j] = cs0[col] + cs1[col] + biass[col];
            }
            eb[d] = y0v[d];                 // t = 0
        }
        #pragma unroll
        for (int t = 1; t <= 10; t++) {
            float a0 = c_A[t*8+0], a1 = c_A[t*8+1], a2 = c_A[t*8+2], a3 = c_A[t*8+3];
            float a4 = c_A[t*8+4], a5 = c_A[t*8+5], a6 = c_A[t*8+6], a7 = c_A[t*8+7];
            #pragma unroll
            for (int d = 0; d < DOF; d++) {
                float v = a2 * wv[d][0];
                v = fmaf(a3, wv[d][1], v);
                v = fmaf(a4, wv[d][2], v);
                v = fmaf(a5, wv[d][3], v);
                v = fmaf(a6, wv[d][4], v);
                float yv = fmaf(a0, y0v[d], a7);
                yv = fmaf(a1, g[d], yv);
                yv = fmaf(v, ku[d], yv);
                eb[t * 7 + d] = yv;
            }
        }
    }
    __syncthreads();

    // ---- coalesced output copy: 128*77 floats = 2464 float4 ----
    const float4* s4 = (const float4*)(sm + EB);
    float4* d4 = (float4*)(out + (size_t)blockIdx.x * RPB * 77);
    #pragma unroll 1
    for (int i = tid; i < (RPB * 77) / 4; i += TPB) d4[i] = s4[i];
}

// ---------------------------------------------------------------------------
// Host: DMP linear map A (8 basis runs of the exact fp32 recursion).
// ---------------------------------------------------------------------------
static float hA[11 * 8];

static void compute_A_host() {
    float c[NB], s2[NB], P[100][NB];
    const float n15 = 11.180339887498949f;     // 5^1.5
    for (int j = 0; j < NB; j++) { c[j] = expf(-0.25f * j); s2[j] = n15 / c[j]; }
    float xv = 1.0f;
    for (int s = 0; s < 100; s++) {
        xv = xv - xv * 0.01f;
        float sum = 0.0f, psi[NB];
        for (int j = 0; j < NB; j++) {
            float d = xv - c[j];
            psi[j] = expf(-0.5f * d * d / s2[j]);
            sum += psi[j];
        }
        for (int j = 0; j < NB; j++) P[s][j] = psi[j] * xv / sum;
    }
    for (int b = 0; b < 8; b++) {              // basis: y0, g, u0..u4, const
        float y = (b == 0) ? 1.0f : 0.0f;
        float gb = (b == 1) ? 1.0f : 0.0f;
        float u[NB];
        for (int j = 0; j < NB; j++) u[j] = (b == 2 + j) ? 1.0f : 0.0f;
        float z = (b == 7) ? 0.05f : 0.0f;
        hA[0 * 8 + b] = y;
        int s = 0;
        for (int tt = 1; tt <= 10; tt++) {
            for (int ss = 0; ss < 10; ss++, s++) {
                float fx = 0.0f;
                for (int j = 0; j < NB; j++) fx += P[s][j] * u[j];
                float dz = 56.25f * (gb - y) - 15.0f * z + fx;
                y = y + z * 0.01f;             // uses old z
                z = z + dz * 0.01f;
            }
            hA[tt * 8 + b] = y;
        }
    }
}

extern "C" void kernel_launch(void* const* d_in, const int* in_sizes, int n_in,
                              void* d_out, int out_size)
{
    const float* x     = (const float*)d_in[0];
    const float* state = (const float*)d_in[1];
    const float* W     = (const float*)d_in[2];
    const float* b     = (const float*)d_in[3];
    float* out = (float*)d_out;

    compute_A_host();
    cudaMemcpyToSymbolAsync(c_A, hA, sizeof(hA), 0, cudaMemcpyHostToDevice);

    cudaFuncSetAttribute(fused_kernel,
                         cudaFuncAttributeMaxDynamicSharedMemorySize, SMEM_TOTAL);
    fused_kernel<<<GRID, TPB, SMEM_TOTAL>>>(x, state, W, b, out);
}